// round 9
// baseline (speedup 1.0000x reference)
#include <cuda_runtime.h>
#include <math.h>
#include <cstdint>

#define Bn 4
#define CI 128
#define CO 128
#define Hn 128
#define Wn 128
#define HW (Hn*Wn)
#define KK 9
#define CIP 136          // padded pixel-row stride (mod 32 = 8 -> conflict-free)

// packed fp32x2 helpers (for offset conv)
#define PACKF2(d, a, b) asm("mov.b64 %0, {%1, %2};" : "=l"(d) : "f"(a), "f"(b))
#define FMAF2(d, a, b, c) asm("fma.rn.f32x2 %0, %1, %2, %3;" : "=l"(d) : "l"(a), "l"(b), "l"(c))
union F2U { unsigned long long u; float2 f; };

// tf32 convert (round to nearest)
#define CVT_TF32(u, f) asm("cvt.rna.tf32.f32 %0, %1;" : "=r"(u) : "f"(f))

// warp-level tensor core MMA: D(16x8) += A(16x8,tf32) * B(8x8,tf32)
__device__ __forceinline__ void mma_tf32(float* c, const uint4& a, uint32_t b0, uint32_t b1) {
    asm volatile("mma.sync.aligned.m16n8k8.row.col.f32.tf32.tf32.f32 "
        "{%0,%1,%2,%3}, {%4,%5,%6,%7}, {%8,%9}, {%0,%1,%2,%3};"
        : "+f"(c[0]), "+f"(c[1]), "+f"(c[2]), "+f"(c[3])
        : "r"(a.x), "r"(a.y), "r"(a.z), "r"(a.w), "r"(b0), "r"(b1));
}

// channel -> storage position: within each 8-group store order 0,4,1,5,2,6,3,7
__device__ __forceinline__ int permc(int c) {
    return (c & ~7) | (((c & 3) << 1) | ((c >> 2) & 1));
}

// ---------------- scratch ----------------
__device__ __align__(16) float g_xT[Bn*HW*CI];       // x in NHWC, channel-permuted
__device__ __align__(16) float g_offp[2][Bn*18*HW];  // partial offset conv
__device__ __align__(16) float g_wF[KK*16*8*32*4];   // weights in A-fragment order (tf32)
__device__ __align__(16) float g_conv[Bn*CO*HW];     // pre-BN output
__device__ float g_scale[CO];
__device__ float g_shift[CO];

// ---------------- K1: NCHW -> NHWC (channel-permuted) transpose of x ----------------
__global__ void k_transpose_x(const float* __restrict__ in) {
    __shared__ float t[32][33];
    int wb = blockIdx.x * 32, cb = blockIdx.y * 32;
    int by = blockIdx.z;
    int b = by >> 7, y = by & 127;
    t[threadIdx.y][threadIdx.x] =
        in[((b*CI + cb + threadIdx.y)*Hn + y)*Wn + wb + threadIdx.x];
    __syncthreads();
    g_xT[(by*Wn + wb + threadIdx.y)*CI + permc(cb + threadIdx.x)] = t[threadIdx.x][threadIdx.y];
}

// ---------------- K2: w_dcn -> A-fragment prepack (tf32) ----------------
// A = weights, M=o(128), K=c (ORIGINAL channel index; B supplies matching channels).
// Fragment m16n8k8: lane l holds a0=(o=ost*16+l/4, c=s*8+l%4), a1=(o+8,c), a2=(o,c+4), a3=(o+8,c+4).
// g_wF[tap][step s][ostripe][lane][4]
__global__ void k_prep_w(const float* __restrict__ w) {
    int i = blockIdx.x * blockDim.x + threadIdx.x;
    if (i >= KK*16*8*32) return;
    int l = i & 31;
    int r = i >> 5;
    int ost = r & 7;  r >>= 3;
    int s = r & 15;
    int tap = r >> 4;
    int o = ost*16 + (l >> 2);
    int c = s*8 + (l & 3);
    float a0 = w[(o*CI + c)*9 + tap];
    float a1 = w[((o+8)*CI + c)*9 + tap];
    float a2 = w[(o*CI + c + 4)*9 + tap];
    float a3 = w[((o+8)*CI + c + 4)*9 + tap];
    uint4 u;
    CVT_TF32(u.x, a0); CVT_TF32(u.y, a1); CVT_TF32(u.z, a2); CVT_TF32(u.w, a3);
    ((uint4*)g_wF)[i] = u;
}

// ---------------- K3: offset conv (18 out ch, 3x3, pad 1), CI split over z ----------------
__global__ __launch_bounds__(128) void k_offset_conv(
    const float* __restrict__ x, const float* __restrict__ w_off,
    const float* __restrict__ b_off) {
    __shared__ __align__(16) float sw[64*9*18];
    int h = blockIdx.x, b = blockIdx.y, z = blockIdx.z;
    int c0 = z * 64;
    int w = threadIdx.x;

    unsigned long long acc2[9];
#pragma unroll
    for (int j = 0; j < 9; j++) acc2[j] = 0ull;

    for (int e = threadIdx.x; e < 64*9*18; e += 128) {
        int cl = e / 162, r = e % 162, t = r / 18, j = r % 18;
        sw[e] = w_off[((j*CI + c0 + cl)*3 + t/3)*3 + t%3];
    }
    __syncthreads();
    for (int cl = 0; cl < 64; cl++) {
        const float* xp = x + (size_t)(b*CI + c0 + cl)*HW;
#pragma unroll
        for (int t = 0; t < 9; t++) {
            int yy = h + t/3 - 1;
            int xx = w + t%3 - 1;
            float xv = (yy >= 0 && yy < Hn && xx >= 0 && xx < Wn)
                     ? xp[yy*Wn + xx] : 0.f;
            unsigned long long xv2;
            PACKF2(xv2, xv, xv);
            const unsigned long long* swp =
                (const unsigned long long*)&sw[(cl*9 + t)*18];
#pragma unroll
            for (int j = 0; j < 9; j++) FMAF2(acc2[j], xv2, swp[j], acc2[j]);
        }
    }
#pragma unroll
    for (int jj = 0; jj < 9; jj++) {
        F2U u; u.u = acc2[jj];
        float b0 = (z == 0) ? b_off[2*jj]     : 0.f;
        float b1 = (z == 0) ? b_off[2*jj + 1] : 0.f;
        g_offp[z][((b*18 + 2*jj    )*Hn + h)*Wn + w] = u.f.x + b0;
        g_offp[z][((b*18 + 2*jj + 1)*Hn + h)*Wn + w] = u.f.y + b1;
    }
}

// ---------------- K4: deformable sampling + mma.sync TF32 GEMM ----------------
// block = (wsplit, h, b): 64 pixels x 128 out channels. 256 threads = 8 warps.
// warp grid: wm = wid>>1 (4 M-warps, 32 o), wc = wid&1 (2 N-warps, 32 pix, 4 t-tiles).
__global__ __launch_bounds__(256, 4) void k_main() {
    __shared__ __align__(16) float sS[64*CIP];   // sampled [pix][cpos], tf32 bits, 34.8 KB

    const int w0  = blockIdx.x * 64;
    const int h   = blockIdx.y;
    const int b   = blockIdx.z;
    const int tid = threadIdx.x;
    const int wid = tid >> 5;
    const int l   = tid & 31;
    const int wm  = wid >> 1;
    const int wc  = wid & 1;

    float acc[2][4][4];
#pragma unroll
    for (int st = 0; st < 2; st++)
#pragma unroll
        for (int t = 0; t < 4; t++)
#pragma unroll
            for (int j = 0; j < 4; j++) acc[st][t][j] = 0.f;

    const int spix = tid >> 3;            // sampler: pixel 0..31 (per pass)
    const int sc   = (tid & 7) * 4;       // sampler: channel-position quad base

    // B lane base: pix-in-tile = l>>2, channel positions 2*(l&3), +1 (== channels l&3, l&3+4)
    const float* bBase = sS + (wc*32 + (l >> 2))*CIP + (l & 3)*2;

    for (int k = 0; k < KK; k++) {
        if (k) __syncthreads();           // protect sS from previous tap's readers
        // --- sample tap k: in-thread corner computation, 2 passes of 32 pixels ---
        const int ky = k / 3, kx = k % 3;
#pragma unroll
        for (int pass = 0; pass < 2; pass++) {
            int px = pass*32 + spix;
            int w = w0 + px;
            int oidx = ((b*18 + 2*k)*Hn + h)*Wn + w;
            float dy = g_offp[0][oidx]      + g_offp[1][oidx];
            float dx = g_offp[0][oidx + HW] + g_offp[1][oidx + HW];
            float ys = (float)(h - 1 + ky) + dy;
            float xs = (float)(w - 1 + kx) + dx;
            float y0f = floorf(ys), x0f = floorf(xs);
            float wy = ys - y0f, wx = xs - x0f;
            int y0 = (int)y0f, x0 = (int)x0f;
            int y1 = y0 + 1, x1 = x0 + 1;
            float vy0 = (y0 >= 0 && y0 < Hn) ? 1.f : 0.f;
            float vy1 = (y1 >= 0 && y1 < Hn) ? 1.f : 0.f;
            float vx0 = (x0 >= 0 && x0 < Wn) ? 1.f : 0.f;
            float vx1 = (x1 >= 0 && x1 < Wn) ? 1.f : 0.f;
            int y0c = min(max(y0, 0), Hn-1), y1c = min(max(y1, 0), Hn-1);
            int x0c = min(max(x0, 0), Wn-1), x1c = min(max(x1, 0), Wn-1);
            int base = b * HW;
            int i0 = (base + y0c*Wn + x0c)*CI;
            int i1 = (base + y0c*Wn + x1c)*CI;
            int i2 = (base + y1c*Wn + x0c)*CI;
            int i3 = (base + y1c*Wn + x1c)*CI;
            float w00 = (1.f - wy)*(1.f - wx)*vy0*vx0;
            float w01 = (1.f - wy)*wx       *vy0*vx1;
            float w10 = wy       *(1.f - wx)*vy1*vx0;
            float w11 = wy       *wx        *vy1*vx1;
#pragma unroll
            for (int cc = 0; cc < CI; cc += 32) {
                int c = cc + sc;
                float4 p0 = *(const float4*)(g_xT + i0 + c);
                float4 p1 = *(const float4*)(g_xT + i1 + c);
                float4 p2 = *(const float4*)(g_xT + i2 + c);
                float4 p3 = *(const float4*)(g_xT + i3 + c);
                float4 v;
                v.x = w00*p0.x + w01*p1.x + w10*p2.x + w11*p3.x;
                v.y = w00*p0.y + w01*p1.y + w10*p2.y + w11*p3.y;
                v.z = w00*p0.z + w01*p1.z + w10*p2.z + w11*p3.z;
                v.w = w00*p0.w + w01*p1.w + w10*p2.w + w11*p3.w;
                uint4 u;
                CVT_TF32(u.x, v.x); CVT_TF32(u.y, v.y);
                CVT_TF32(u.z, v.z); CVT_TF32(u.w, v.w);
                *(uint4*)(sS + px*CIP + c) = u;
            }
        }
        __syncthreads();

        // --- GEMM: 16 K=8 steps; per step 2 A-frag LDG.128 + 4 B LDS.64 ---
        const uint4* aBase = (const uint4*)g_wF + ((k*16)*8 + 2*wm)*32 + l;
#pragma unroll 2
        for (int s = 0; s < 16; s++) {
            uint4 aF0 = aBase[s*256];          // ostripe 2*wm
            uint4 aF1 = aBase[s*256 + 32];     // ostripe 2*wm + 1
            const float* bp = bBase + s*8;
#pragma unroll
            for (int t = 0; t < 4; t++) {
                uint2 bv = *(const uint2*)(bp + t*8*CIP);
                mma_tf32(acc[0][t], aF0, bv.x, bv.y);
                mma_tf32(acc[1][t], aF1, bv.x, bv.y);
            }
        }
    }

    // --- epilogue: D[o][pix] fragments -> g_conv (NCHW) ---
#pragma unroll
    for (int st = 0; st < 2; st++) {
        int o = 32*wm + st*16 + (l >> 2);
#pragma unroll
        for (int t = 0; t < 4; t++) {
            int px = w0 + wc*32 + t*8 + 2*(l & 3);
            float* d = g_conv + ((size_t)(b*CO + o)*Hn + h)*Wn + px;
            *(float2*)d            = make_float2(acc[st][t][0], acc[st][t][1]);
            *(float2*)(d + 8*HW)   = make_float2(acc[st][t][2], acc[st][t][3]);
        }
    }
}

// ---------------- K5: BN stats per channel ----------------
__global__ void k_bn_stats(const float* __restrict__ gamma,
                           const float* __restrict__ beta) {
    int o = blockIdx.x, tid = threadIdx.x;
    float s = 0.f, s2 = 0.f;
    for (int b = 0; b < Bn; b++) {
        const float* p = g_conv + (size_t)(b*CO + o)*HW;
        for (int i = tid; i < HW; i += 256) {
            float v = p[i];
            s += v;
            s2 = fmaf(v, v, s2);
        }
    }
    __shared__ float rs[8], rs2[8];
#pragma unroll
    for (int off = 16; off; off >>= 1) {
        s  += __shfl_down_sync(0xffffffffu, s,  off);
        s2 += __shfl_down_sync(0xffffffffu, s2, off);
    }
    if ((tid & 31) == 0) { rs[tid >> 5] = s; rs2[tid >> 5] = s2; }
    __syncthreads();
    if (tid < 32) {
        s  = (tid < 8) ? rs[tid]  : 0.f;
        s2 = (tid < 8) ? rs2[tid] : 0.f;
#pragma unroll
        for (int off = 4; off; off >>= 1) {
            s  += __shfl_down_sync(0xffffffffu, s,  off);
            s2 += __shfl_down_sync(0xffffffffu, s2, off);
        }
        if (tid == 0) {
            float inv_n = 1.f / (float)(Bn*HW);
            float mean = s * inv_n;
            float var  = s2 * inv_n - mean*mean;
            float r = 1.f / sqrtf(var + 0.001f);
            float sc = gamma[o] * r;
            g_scale[o] = sc;
            g_shift[o] = beta[o] - mean*sc;
        }
    }
}

// ---------------- K6: apply BN + ReLU ----------------
__global__ void k_bn_apply(float* __restrict__ out) {
    int i = blockIdx.x * blockDim.x + threadIdx.x;
    int ch = (i >> 12) & 127;
    float4 v = ((const float4*)g_conv)[i];
    float sc = g_scale[ch], sh = g_shift[ch];
    v.x = fmaxf(fmaf(v.x, sc, sh), 0.f);
    v.y = fmaxf(fmaf(v.y, sc, sh), 0.f);
    v.z = fmaxf(fmaf(v.z, sc, sh), 0.f);
    v.w = fmaxf(fmaf(v.w, sc, sh), 0.f);
    ((float4*)out)[i] = v;
}

// ---------------- launch ----------------
extern "C" void kernel_launch(void* const* d_in, const int* in_sizes, int n_in,
                              void* d_out, int out_size) {
    const float* x     = (const float*)d_in[0];
    const float* w_off = (const float*)d_in[1];
    const float* b_off = (const float*)d_in[2];
    const float* w_dcn = (const float*)d_in[3];
    const float* gamma = (const float*)d_in[4];
    const float* beta  = (const float*)d_in[5];
    float* out = (float*)d_out;

    k_transpose_x<<<dim3(Wn/32, CI/32, Bn*Hn), dim3(32, 32)>>>(x);
    k_prep_w<<<(KK*16*8*32 + 255)/256, 256>>>(w_dcn);
    k_offset_conv<<<dim3(Hn, Bn, 2), 128>>>(x, w_off, b_off);
    k_main<<<dim3(2, Hn, Bn), 256>>>();
    k_bn_stats<<<CO, 256>>>(gamma, beta);
    k_bn_apply<<<(Bn*CO*HW/4)/256, 256>>>(out);
}

// round 10
// speedup vs baseline: 1.0440x; 1.0440x over previous
#include <cuda_runtime.h>
#include <math.h>
#include <cstdint>

#define Bn 4
#define CI 128
#define CO 128
#define Hn 128
#define Wn 128
#define HW (Hn*Wn)
#define KK 9
#define CIP 136          // pixel-row stride; conflict-free for STS.128 and LDS.64

// packed fp32x2 helpers (for offset conv)
#define PACKF2(d, a, b) asm("mov.b64 %0, {%1, %2};" : "=l"(d) : "f"(a), "f"(b))
#define FMAF2(d, a, b, c) asm("fma.rn.f32x2 %0, %1, %2, %3;" : "=l"(d) : "l"(a), "l"(b), "l"(c))
union F2U { unsigned long long u; float2 f; };

// tf32 convert (round to nearest)
#define CVT_TF32(u, f) asm("cvt.rna.tf32.f32 %0, %1;" : "=r"(u) : "f"(f))

// warp-level tensor core MMA: D(16x8) += A(16x8,tf32) * B(8x8,tf32)
__device__ __forceinline__ void mma_tf32(float* c, const uint4& a, uint32_t b0, uint32_t b1) {
    asm volatile("mma.sync.aligned.m16n8k8.row.col.f32.tf32.tf32.f32 "
        "{%0,%1,%2,%3}, {%4,%5,%6,%7}, {%8,%9}, {%0,%1,%2,%3};"
        : "+f"(c[0]), "+f"(c[1]), "+f"(c[2]), "+f"(c[3])
        : "r"(a.x), "r"(a.y), "r"(a.z), "r"(a.w), "r"(b0), "r"(b1));
}

// channel -> storage position: within each 8-group store order 0,4,1,5,2,6,3,7
__device__ __forceinline__ int permc(int c) {
    return (c & ~7) | (((c & 3) << 1) | ((c >> 2) & 1));
}

// ---------------- scratch ----------------
__device__ __align__(16) float g_xT[Bn*HW*CI];       // x in NHWC, channel-permuted
__device__ __align__(16) float g_offp[2][Bn*18*HW];  // partial offset conv
__device__ __align__(16) float g_wF[KK*16*8*32*4];   // weights in A-fragment order (tf32)
__device__ __align__(16) float g_conv[Bn*CO*HW];     // pre-BN output
__device__ float g_stat[2*CO];                       // fused BN sums: [o]=sum, [128+o]=sumsq
__device__ float g_scale[CO];
__device__ float g_shift[CO];

// ---------------- K1: NCHW -> NHWC (channel-permuted) transpose of x ----------------
__global__ void k_transpose_x(const float* __restrict__ in) {
    __shared__ float t[32][33];
    int wb = blockIdx.x * 32, cb = blockIdx.y * 32;
    int by = blockIdx.z;
    int b = by >> 7, y = by & 127;
    t[threadIdx.y][threadIdx.x] =
        in[((b*CI + cb + threadIdx.y)*Hn + y)*Wn + wb + threadIdx.x];
    __syncthreads();
    g_xT[(by*Wn + wb + threadIdx.y)*CI + permc(cb + threadIdx.x)] = t[threadIdx.x][threadIdx.y];
}

// ---------------- K2: w_dcn -> A-fragment prepack (tf32); also zero g_stat ----------------
__global__ void k_prep_w(const float* __restrict__ w) {
    if (blockIdx.x == 0 && threadIdx.x < 2*CO) g_stat[threadIdx.x] = 0.f;
    int i = blockIdx.x * blockDim.x + threadIdx.x;
    if (i >= KK*16*8*32) return;
    int l = i & 31;
    int r = i >> 5;
    int ost = r & 7;  r >>= 3;
    int s = r & 15;
    int tap = r >> 4;
    int o = ost*16 + (l >> 2);
    int c = s*8 + (l & 3);
    float a0 = w[(o*CI + c)*9 + tap];
    float a1 = w[((o+8)*CI + c)*9 + tap];
    float a2 = w[(o*CI + c + 4)*9 + tap];
    float a3 = w[((o+8)*CI + c + 4)*9 + tap];
    uint4 u;
    CVT_TF32(u.x, a0); CVT_TF32(u.y, a1); CVT_TF32(u.z, a2); CVT_TF32(u.w, a3);
    ((uint4*)g_wF)[i] = u;
}

// ---------------- K3: offset conv (18 out ch, 3x3, pad 1), CI split over z ----------------
__global__ __launch_bounds__(128) void k_offset_conv(
    const float* __restrict__ x, const float* __restrict__ w_off,
    const float* __restrict__ b_off) {
    __shared__ __align__(16) float sw[64*9*18];
    int h = blockIdx.x, b = blockIdx.y, z = blockIdx.z;
    int c0 = z * 64;
    int w = threadIdx.x;

    unsigned long long acc2[9];
#pragma unroll
    for (int j = 0; j < 9; j++) acc2[j] = 0ull;

    for (int e = threadIdx.x; e < 64*9*18; e += 128) {
        int cl = e / 162, r = e % 162, t = r / 18, j = r % 18;
        sw[e] = w_off[((j*CI + c0 + cl)*3 + t/3)*3 + t%3];
    }
    __syncthreads();
    for (int cl = 0; cl < 64; cl++) {
        const float* xp = x + (size_t)(b*CI + c0 + cl)*HW;
#pragma unroll
        for (int t = 0; t < 9; t++) {
            int yy = h + t/3 - 1;
            int xx = w + t%3 - 1;
            float xv = (yy >= 0 && yy < Hn && xx >= 0 && xx < Wn)
                     ? xp[yy*Wn + xx] : 0.f;
            unsigned long long xv2;
            PACKF2(xv2, xv, xv);
            const unsigned long long* swp =
                (const unsigned long long*)&sw[(cl*9 + t)*18];
#pragma unroll
            for (int j = 0; j < 9; j++) FMAF2(acc2[j], xv2, swp[j], acc2[j]);
        }
    }
#pragma unroll
    for (int jj = 0; jj < 9; jj++) {
        F2U u; u.u = acc2[jj];
        float b0 = (z == 0) ? b_off[2*jj]     : 0.f;
        float b1 = (z == 0) ? b_off[2*jj + 1] : 0.f;
        g_offp[z][((b*18 + 2*jj    )*Hn + h)*Wn + w] = u.f.x + b0;
        g_offp[z][((b*18 + 2*jj + 1)*Hn + h)*Wn + w] = u.f.y + b1;
    }
}

// ---------------- K4: deformable sampling + mma.sync TF32 GEMM + fused BN stats ----------------
// block = (h, b): 128 pixels x 128 out channels. 256 threads = 8 warps.
// warp grid: wm = wid>>1 (4 M-warps, 32 o), wc = wid&1 (2 N-warps, 64 px, 8 t-tiles).
#define OFF_S    0                       // float [128][CIP] tf32 bits  69632 B
#define OFF_OFF  69632                   // float [18][128] offset sums  9216 B
#define SMEM_K4  (OFF_OFF + 9216)

__global__ __launch_bounds__(256, 2) void k_main() {
    extern __shared__ __align__(16) char smem[];
    float* sS   = (float*)(smem + OFF_S);
    float* sOff = (float*)(smem + OFF_OFF);

    const int h   = blockIdx.x;
    const int b   = blockIdx.y;
    const int tid = threadIdx.x;
    const int wid = tid >> 5;
    const int l   = tid & 31;
    const int wm  = wid >> 1;
    const int wc  = wid & 1;

    // --- prefetch per-pixel offset sums for all taps (coalesced) ---
    for (int j = tid; j < 18*128; j += 256) {
        int gi = ((b*18 + (j >> 7))*Hn + h)*Wn + (j & 127);
        sOff[j] = g_offp[0][gi] + g_offp[1][gi];
    }

    float acc[2][8][4];
#pragma unroll
    for (int st = 0; st < 2; st++)
#pragma unroll
        for (int t = 0; t < 8; t++)
#pragma unroll
            for (int j = 0; j < 4; j++) acc[st][t][j] = 0.f;

    const int spix = tid >> 3;            // sampler: pixel 0..31 (per pass)
    const int sc   = (tid & 7) * 4;       // sampler: channel-position quad base

    // B lane base: pix = wc*64 + l>>2 (+ t*8); positions 2(l&3), +1 == channels s*8+(l&3), +4
    const float* bBase = sS + (wc*64 + (l >> 2))*CIP + (l & 3)*2;

    __syncthreads();                      // sOff ready

    for (int k = 0; k < KK; k++) {
        if (k) __syncthreads();           // protect sS from previous tap's readers
        const int ky = k / 3, kx = k % 3;
        const float* dyp = sOff + (2*k)*128;
        const float* dxp = sOff + (2*k + 1)*128;
#pragma unroll
        for (int pass = 0; pass < 4; pass++) {
            int px = pass*32 + spix;
            float dy = dyp[px];
            float dx = dxp[px];
            float ys = (float)(h - 1 + ky) + dy;
            float xs = (float)(px - 1 + kx) + dx;
            float y0f = floorf(ys), x0f = floorf(xs);
            float wy = ys - y0f, wx = xs - x0f;
            int y0 = (int)y0f, x0 = (int)x0f;
            int y1 = y0 + 1, x1 = x0 + 1;
            float vy0 = (y0 >= 0 && y0 < Hn) ? 1.f : 0.f;
            float vy1 = (y1 >= 0 && y1 < Hn) ? 1.f : 0.f;
            float vx0 = (x0 >= 0 && x0 < Wn) ? 1.f : 0.f;
            float vx1 = (x1 >= 0 && x1 < Wn) ? 1.f : 0.f;
            int y0c = min(max(y0, 0), Hn-1), y1c = min(max(y1, 0), Hn-1);
            int x0c = min(max(x0, 0), Wn-1), x1c = min(max(x1, 0), Wn-1);
            int base = b * HW;
            int i0 = (base + y0c*Wn + x0c)*CI;
            int i1 = (base + y0c*Wn + x1c)*CI;
            int i2 = (base + y1c*Wn + x0c)*CI;
            int i3 = (base + y1c*Wn + x1c)*CI;
            float w00 = (1.f - wy)*(1.f - wx)*vy0*vx0;
            float w01 = (1.f - wy)*wx       *vy0*vx1;
            float w10 = wy       *(1.f - wx)*vy1*vx0;
            float w11 = wy       *wx        *vy1*vx1;
#pragma unroll
            for (int cc = 0; cc < CI; cc += 32) {
                int c = cc + sc;
                float4 p0 = *(const float4*)(g_xT + i0 + c);
                float4 p1 = *(const float4*)(g_xT + i1 + c);
                float4 p2 = *(const float4*)(g_xT + i2 + c);
                float4 p3 = *(const float4*)(g_xT + i3 + c);
                float4 v;
                v.x = w00*p0.x + w01*p1.x + w10*p2.x + w11*p3.x;
                v.y = w00*p0.y + w01*p1.y + w10*p2.y + w11*p3.y;
                v.z = w00*p0.z + w01*p1.z + w10*p2.z + w11*p3.z;
                v.w = w00*p0.w + w01*p1.w + w10*p2.w + w11*p3.w;
                uint4 u;
                CVT_TF32(u.x, v.x); CVT_TF32(u.y, v.y);
                CVT_TF32(u.z, v.z); CVT_TF32(u.w, v.w);
                *(uint4*)(sS + px*CIP + c) = u;
            }
        }
        __syncthreads();

        // --- GEMM: 16 K=8 steps; per step 2 A-frag LDG.128 + 8 B LDS.64 ---
        const uint4* aBase = (const uint4*)g_wF + ((k*16)*8 + 2*wm)*32 + l;
#pragma unroll 2
        for (int s = 0; s < 16; s++) {
            uint4 aF0 = aBase[s*256];          // ostripe 2*wm
            uint4 aF1 = aBase[s*256 + 32];     // ostripe 2*wm + 1
            const float* bp = bBase + s*8;
#pragma unroll
            for (int t = 0; t < 8; t++) {
                uint2 bv = *(const uint2*)(bp + t*8*CIP);
                mma_tf32(acc[0][t], aF0, bv.x, bv.y);
                mma_tf32(acc[1][t], aF1, bv.x, bv.y);
            }
        }
    }

    // --- epilogue: D[o][pix] fragments -> g_conv (NCHW) ---
#pragma unroll
    for (int st = 0; st < 2; st++) {
        int o = 32*wm + st*16 + (l >> 2);
#pragma unroll
        for (int t = 0; t < 8; t++) {
            int px = wc*64 + t*8 + 2*(l & 3);
            float* d = g_conv + ((size_t)(b*CO + o)*Hn + h)*Wn + px;
            *(float2*)d            = make_float2(acc[st][t][0], acc[st][t][1]);
            *(float2*)(d + 8*HW)   = make_float2(acc[st][t][2], acc[st][t][3]);
        }
    }

    // --- fused BN stats: per-thread partials over 16 px for 4 o-rows, quad-reduce, atomic ---
    {
        float s[4] = {0.f, 0.f, 0.f, 0.f};   // o0, o0+8, o0+16, o0+24
        float q[4] = {0.f, 0.f, 0.f, 0.f};
#pragma unroll
        for (int st = 0; st < 2; st++)
#pragma unroll
            for (int t = 0; t < 8; t++) {
                float a0 = acc[st][t][0], a1 = acc[st][t][1];
                float a2 = acc[st][t][2], a3 = acc[st][t][3];
                s[2*st]   += a0 + a1;  q[2*st]   += a0*a0 + a1*a1;
                s[2*st+1] += a2 + a3;  q[2*st+1] += a2*a2 + a3*a3;
            }
#pragma unroll
        for (int d = 1; d < 4; d <<= 1)
#pragma unroll
            for (int j = 0; j < 4; j++) {
                s[j] += __shfl_xor_sync(0xffffffffu, s[j], d);
                q[j] += __shfl_xor_sync(0xffffffffu, q[j], d);
            }
        if ((l & 3) == 0) {
            int o0 = 32*wm + (l >> 2);
#pragma unroll
            for (int j = 0; j < 4; j++) {
                int o = o0 + 8*j;   // j: 0->o0, 1->o0+8, 2->o0+16, 3->o0+24
                int jj = (j == 1) ? 1 : (j == 2) ? 2 : (j == 3) ? 3 : 0;
                atomicAdd(&g_stat[o], s[jj]);
                atomicAdd(&g_stat[CO + o], q[jj]);
            }
        }
    }
}

// ---------------- K5: BN finalize (tiny) ----------------
__global__ void k_bn_finalize(const float* __restrict__ gamma,
                              const float* __restrict__ beta) {
    int o = threadIdx.x;
    float inv_n = 1.f / (float)(Bn*HW);
    float mean = g_stat[o] * inv_n;
    float var  = g_stat[CO + o] * inv_n - mean*mean;
    float r = rsqrtf(var + 0.001f);
    float sc = gamma[o] * r;
    g_scale[o] = sc;
    g_shift[o] = beta[o] - mean*sc;
}

// ---------------- K6: apply BN + ReLU ----------------
__global__ void k_bn_apply(float* __restrict__ out) {
    int i = blockIdx.x * blockDim.x + threadIdx.x;
    int ch = (i >> 12) & 127;
    float4 v = ((const float4*)g_conv)[i];
    float sc = g_scale[ch], sh = g_shift[ch];
    v.x = fmaxf(fmaf(v.x, sc, sh), 0.f);
    v.y = fmaxf(fmaf(v.y, sc, sh), 0.f);
    v.z = fmaxf(fmaf(v.z, sc, sh), 0.f);
    v.w = fmaxf(fmaf(v.w, sc, sh), 0.f);
    ((float4*)out)[i] = v;
}

// ---------------- launch ----------------
extern "C" void kernel_launch(void* const* d_in, const int* in_sizes, int n_in,
                              void* d_out, int out_size) {
    const float* x     = (const float*)d_in[0];
    const float* w_off = (const float*)d_in[1];
    const float* b_off = (const float*)d_in[2];
    const float* w_dcn = (const float*)d_in[3];
    const float* gamma = (const float*)d_in[4];
    const float* beta  = (const float*)d_in[5];
    float* out = (float*)d_out;

    cudaFuncSetAttribute(k_main, cudaFuncAttributeMaxDynamicSharedMemorySize, SMEM_K4);

    k_transpose_x<<<dim3(Wn/32, CI/32, Bn*Hn), dim3(32, 32)>>>(x);
    k_prep_w<<<(KK*16*8*32 + 255)/256, 256>>>(w_dcn);
    k_offset_conv<<<dim3(Hn, Bn, 2), 128>>>(x, w_off, b_off);
    k_main<<<dim3(Hn, Bn), 256, SMEM_K4>>>();
    k_bn_finalize<<<1, CO>>>(gamma, beta);
    k_bn_apply<<<(Bn*CO*HW/4)/256, 256>>>(out);
}